// round 15
// baseline (speedup 1.0000x reference)
#include <cuda_runtime.h>
#include <cuda_bf16.h>
#include <math.h>
#include <stdint.h>

#define B_    4
#define S_    1024
#define E_    1024
#define H_    16
#define DH_   64

// ---------------- scratch ----------------
__device__ float g_qn [B_ * S_ * E_];
__device__ __nv_bfloat16 g_ash[3 * B_ * S_ * E_];
__device__ __nv_bfloat16 g_asl[3 * B_ * S_ * E_];
__device__ __nv_bfloat16 g_wh[4 * E_ * E_];
__device__ __nv_bfloat16 g_wl[4 * E_ * E_];
__device__ __nv_bfloat16 g_qh[B_ * S_ * E_];
__device__ __nv_bfloat16 g_ql[B_ * S_ * E_];
__device__ __nv_bfloat16 g_kh[B_ * S_ * E_];
__device__ __nv_bfloat16 g_kl[B_ * S_ * E_];
__device__ __nv_bfloat16 g_vh[B_ * S_ * E_];
__device__ __nv_bfloat16 g_vl[B_ * S_ * E_];
__device__ __nv_bfloat16 g_vth[B_ * S_ * E_];
__device__ __nv_bfloat16 g_vtl[B_ * S_ * E_];

// ---------------- PTX helpers ----------------
__device__ __forceinline__ uint32_t smem_u32(const void* p) {
    uint32_t a;
    asm("{ .reg .u64 t; cvta.to.shared.u64 t, %1; cvt.u32.u64 %0, t; }" : "=r"(a) : "l"(p));
    return a;
}
__device__ __forceinline__ void cp_async16(uint32_t s, const void* g) {
    asm volatile("cp.async.cg.shared.global [%0], [%1], 16;" :: "r"(s), "l"(g));
}
__device__ __forceinline__ void cp_commit() { asm volatile("cp.async.commit_group;" ::: "memory"); }
template<int N> __device__ __forceinline__ void cp_wait() { asm volatile("cp.async.wait_group %0;" :: "n"(N) : "memory"); }

__device__ __forceinline__ void ldmx4(uint32_t* r, uint32_t addr) {
    asm volatile("ldmatrix.sync.aligned.m8n8.x4.shared.b16 {%0,%1,%2,%3}, [%4];"
        : "=r"(r[0]), "=r"(r[1]), "=r"(r[2]), "=r"(r[3]) : "r"(addr));
}
__device__ __forceinline__ void mma16816(float* d, const uint32_t* a, const uint32_t* b) {
    asm volatile("mma.sync.aligned.m16n8k16.row.col.f32.bf16.bf16.f32 "
        "{%0,%1,%2,%3}, {%4,%5,%6,%7}, {%8,%9}, {%0,%1,%2,%3};"
        : "+f"(d[0]), "+f"(d[1]), "+f"(d[2]), "+f"(d[3])
        : "r"(a[0]), "r"(a[1]), "r"(a[2]), "r"(a[3]), "r"(b[0]), "r"(b[1]));
}
__device__ __forceinline__ uint32_t pack_bf2(__nv_bfloat16 a, __nv_bfloat16 b) {
    uint16_t ua = *(uint16_t*)&a, ub = *(uint16_t*)&b;
    return (uint32_t)ua | ((uint32_t)ub << 16);
}
__device__ __forceinline__ void split1(float v, __nv_bfloat16& h, __nv_bfloat16& l) {
    h = __float2bfloat16_rn(v);
    l = __float2bfloat16_rn(v - __bfloat162float(h));
}

// ---------------- layernorm + Q split ----------------
__global__ __launch_bounds__(256) void ln_split_kernel(const float* __restrict__ x,
                                                       const float* __restrict__ gamma,
                                                       const float* __restrict__ beta,
                                                       float* __restrict__ y,
                                                       __nv_bfloat16* __restrict__ sh,
                                                       __nv_bfloat16* __restrict__ sl) {
    __shared__ float red[32];
    int row = blockIdx.x;
    int tid = threadIdx.x;
    const float* xr = x + (size_t)row * 1024;

    float v[4];
    float s = 0.f;
#pragma unroll
    for (int i = 0; i < 4; i++) { v[i] = xr[tid + 256 * i]; s += v[i]; }

    for (int off = 16; off; off >>= 1) s += __shfl_xor_sync(0xffffffffu, s, off);
    int lane = tid & 31, wid = tid >> 5;
    if (lane == 0) red[wid] = s;
    __syncthreads();
    if (wid == 0) {
        float t = (lane < 8) ? red[lane] : 0.f;
        for (int off = 4; off; off >>= 1) t += __shfl_xor_sync(0xffffffffu, t, off);
        if (lane == 0) red[0] = t;
    }
    __syncthreads();
    float mean = red[0] * (1.f / 1024.f);
    __syncthreads();

    float vs = 0.f;
#pragma unroll
    for (int i = 0; i < 4; i++) { float d = v[i] - mean; vs += d * d; }
    for (int off = 16; off; off >>= 1) vs += __shfl_xor_sync(0xffffffffu, vs, off);
    if (lane == 0) red[wid] = vs;
    __syncthreads();
    if (wid == 0) {
        float t = (lane < 8) ? red[lane] : 0.f;
        for (int off = 4; off; off >>= 1) t += __shfl_xor_sync(0xffffffffu, t, off);
        if (lane == 0) red[0] = t;
    }
    __syncthreads();
    float var = red[0] * (1.f / 1024.f);
    float rstd = rsqrtf(var + 1e-5f);

    float* yr = y + (size_t)row * 1024;
#pragma unroll
    for (int i = 0; i < 4; i++) {
        int c = tid + 256 * i;
        float o = (v[i] - mean) * rstd * gamma[c] + beta[c];
        yr[c] = o;
        __nv_bfloat16 hh, ll;
        split1(o, hh, ll);
        sh[(size_t)row * 1024 + c] = hh;
        sl[(size_t)row * 1024 + c] = ll;
    }
}

// ---------------- batched fp32 -> bf16 split (key, value) ----------------
__global__ __launch_bounds__(256) void split2_kernel(const float* __restrict__ key,
                                                     const float* __restrict__ value,
                                                     __nv_bfloat16* __restrict__ hi,
                                                     __nv_bfloat16* __restrict__ lo) {
    const float* x = blockIdx.y ? value : key;
    size_t slot = (size_t)(blockIdx.y + 1) * (B_ * S_ * E_);
    int i = blockIdx.x * 256 + threadIdx.x;
    float4 v = *(const float4*)(x + (size_t)i * 4);
    float f[4] = {v.x, v.y, v.z, v.w};
    __nv_bfloat16 h[4], l[4];
#pragma unroll
    for (int j = 0; j < 4; j++) split1(f[j], h[j], l[j]);
    *(uint2*)(hi + slot + (size_t)i * 4) = *(uint2*)h;
    *(uint2*)(lo + slot + (size_t)i * 4) = *(uint2*)l;
}

// ---------------- batched W -> W^T split ----------------
__global__ __launch_bounds__(256) void tsplit4_kernel(const float* __restrict__ w0,
                                                      const float* __restrict__ w1,
                                                      const float* __restrict__ w2,
                                                      const float* __restrict__ w3) {
    __shared__ float t[32][33];
    const float* W = (blockIdx.z == 0) ? w0 : (blockIdx.z == 1) ? w1 : (blockIdx.z == 2) ? w2 : w3;
    size_t slot = (size_t)blockIdx.z * (E_ * E_);
    int bx = blockIdx.x * 32;
    int by = blockIdx.y * 32;
    int x = threadIdx.x & 31, y = threadIdx.x >> 5;
#pragma unroll
    for (int i = 0; i < 32; i += 8)
        t[y + i][x] = W[(size_t)(by + y + i) * 1024 + bx + x];
    __syncthreads();
#pragma unroll
    for (int i = 0; i < 32; i += 8) {
        int n = bx + y + i, k = by + x;
        __nv_bfloat16 h, l;
        split1(t[x][y + i], h, l);
        g_wh[slot + (size_t)n * 1024 + k] = h;
        g_wl[slot + (size_t)n * 1024 + k] = l;
    }
}

// ---------------- HMMA bf16x3 GEMM core ----------------
#define LDK 40
static constexpr int MAT_H  = 128 * LDK;
static constexpr int GEMM_SMEM = 2 * 4 * MAT_H * 2;   // 81920 bytes

template<int MODE>
__device__ __forceinline__ void hgemm_core(const __nv_bfloat16* Ah, const __nv_bfloat16* Al,
                                           const __nv_bfloat16* Bth, const __nv_bfloat16* Btl,
                                           float* C, __nv_bfloat16* Oh, __nv_bfloat16* Ol,
                                           const float* bias, const float* qn, const int* qlen,
                                           int row0, int col0, uint32_t sbase) {
    const int tid = threadIdx.x;
    const int wid = tid >> 5, lane = tid & 31;

    const __nv_bfloat16* gp0 = Ah  + (size_t)row0 * 1024;
    const __nv_bfloat16* gp1 = Al  + (size_t)row0 * 1024;
    const __nv_bfloat16* gp2 = Bth + (size_t)col0 * 1024;
    const __nv_bfloat16* gp3 = Btl + (size_t)col0 * 1024;

    const int lr = tid >> 2;
    const int lq = (tid & 3) * 8;

    auto load_stage = [&](int st, int kt) {
        uint32_t sb = sbase + (uint32_t)st * 4 * MAT_H * 2;
        const __nv_bfloat16* gs[4] = {gp0 + kt * 32, gp1 + kt * 32, gp2 + kt * 32, gp3 + kt * 32};
#pragma unroll
        for (int m = 0; m < 4; m++) {
#pragma unroll
            for (int i = 0; i < 2; i++) {
                int r = lr + i * 64;
                cp_async16(sb + (uint32_t)(m * MAT_H + r * LDK + lq) * 2,
                           gs[m] + (size_t)r * 1024 + lq);
            }
        }
    };

    load_stage(0, 0);
    cp_commit();

    float acc[2][8][4];
#pragma unroll
    for (int mt = 0; mt < 2; mt++)
#pragma unroll
        for (int nt = 0; nt < 8; nt++)
#pragma unroll
            for (int j = 0; j < 4; j++) acc[mt][nt][j] = 0.f;

    const int warp_m = (wid & 3) * 32;
    const int warp_n = (wid >> 2) * 64;

    const uint32_t a_off = (uint32_t)((warp_m + (lane & 15)) * LDK + (lane >> 4) * 8);
    const uint32_t b_off = (uint32_t)((warp_n + (lane >> 4) * 8 + (lane & 7)) * LDK + ((lane >> 3) & 1) * 8);

    for (int kt = 0; kt < 32; kt++) {
        const int st = kt & 1;
        if (kt + 1 < 32) {
            load_stage(st ^ 1, kt + 1);
            cp_commit();
            cp_wait<1>();
        } else {
            cp_wait<0>();
        }
        __syncthreads();

        const uint32_t Abase = sbase + (uint32_t)st * 4 * MAT_H * 2;
        const uint32_t Bbase = Abase + 2 * MAT_H * 2;
#pragma unroll
        for (int ks = 0; ks < 2; ks++) {
            const uint32_t kadd = (uint32_t)(ks * 16) * 2;
            uint32_t a_h[2][4], a_l[2][4];
#pragma unroll
            for (int mt = 0; mt < 2; mt++) {
                uint32_t off = (a_off + (uint32_t)(mt * 16) * LDK) * 2 + kadd;
                ldmx4(a_h[mt], Abase + off);
                ldmx4(a_l[mt], Abase + MAT_H * 2 + off);
            }
#pragma unroll
            for (int np = 0; np < 4; np++) {
                uint32_t b_h[4], b_l[4];
                uint32_t off = (b_off + (uint32_t)(np * 16) * LDK) * 2 + kadd;
                ldmx4(b_h, Bbase + off);
                ldmx4(b_l, Bbase + MAT_H * 2 + off);
#pragma unroll
                for (int mt = 0; mt < 2; mt++) {
                    mma16816(acc[mt][np * 2 + 0], a_h[mt], b_h + 0);
                    mma16816(acc[mt][np * 2 + 0], a_h[mt], b_l + 0);
                    mma16816(acc[mt][np * 2 + 0], a_l[mt], b_h + 0);
                    mma16816(acc[mt][np * 2 + 1], a_h[mt], b_h + 2);
                    mma16816(acc[mt][np * 2 + 1], a_h[mt], b_l + 2);
                    mma16816(acc[mt][np * 2 + 1], a_l[mt], b_h + 2);
                }
            }
        }
        __syncthreads();
    }

#pragma unroll
    for (int mt = 0; mt < 2; mt++) {
        int r0i = row0 + warp_m + mt * 16 + (lane >> 2);
#pragma unroll
        for (int half = 0; half < 2; half++) {
            int r = r0i + half * 8;
            float keep = 1.f;
            if (MODE == 1) {
                int bb = r >> 10, ss = r & 1023;
                keep = (ss < qlen[bb]) ? 1.f : 0.f;
            }
#pragma unroll
            for (int nt = 0; nt < 8; nt++) {
                int c = col0 + warp_n + nt * 8 + (lane & 3) * 2;
                float v0 = acc[mt][nt][half * 2 + 0];
                float v1 = acc[mt][nt][half * 2 + 1];
                if (MODE == 1) {
                    const float2 bi = *(const float2*)&bias[c];
                    const float2 q2 = *(const float2*)&qn[(size_t)r * 1024 + c];
                    v0 = (v0 + bi.x) * keep + q2.x;
                    v1 = (v1 + bi.y) * keep + q2.y;
                    *(float2*)&C[(size_t)r * 1024 + c] = make_float2(v0, v1);
                } else {
                    __nv_bfloat16 h0, h1, l0, l1;
                    split1(v0, h0, l0);
                    split1(v1, h1, l1);
                    *(uint32_t*)&Oh[(size_t)r * 1024 + c] = pack_bf2(h0, h1);
                    *(uint32_t*)&Ol[(size_t)r * 1024 + c] = pack_bf2(l0, l1);
                }
            }
        }
    }
}

// __launch_bounds__(256, 2): regs already exactly at the 2-block cap (128) -> no spill,
// marks kernel for dual residency.
__global__ __launch_bounds__(256, 2) void hgemm_proj(const __nv_bfloat16* __restrict__ ash,
                                                     const __nv_bfloat16* __restrict__ asl,
                                                     const __nv_bfloat16* __restrict__ wth,
                                                     const __nv_bfloat16* __restrict__ wtl,
                                                     __nv_bfloat16* __restrict__ oh,
                                                     __nv_bfloat16* __restrict__ ol) {
    extern __shared__ __nv_bfloat16 smb[];
    hgemm_core<0>(ash, asl, wth, wtl, nullptr, oh, ol, nullptr, nullptr, nullptr,
                  blockIdx.y * 128, blockIdx.x * 128, smem_u32(smb));
}

__global__ __launch_bounds__(256, 2) void hgemm_out(const __nv_bfloat16* __restrict__ ash,
                                                    const __nv_bfloat16* __restrict__ asl,
                                                    float* __restrict__ C,
                                                    const float* __restrict__ bias,
                                                    const float* __restrict__ qn,
                                                    const int* __restrict__ qlen) {
    extern __shared__ __nv_bfloat16 smb[];
    int row0 = blockIdx.y * 128;
    int col0 = blockIdx.x * 128;
    {
        int bb = row0 >> 10, ss = row0 & 1023;
        if (ss >= qlen[bb]) {
            int tid = threadIdx.x;
            int r = row0 + (tid >> 1);
            int c0 = col0 + (tid & 1) * 64;
            const float4* src = (const float4*)&qn[(size_t)r * 1024 + c0];
            float4* dst = (float4*)&C[(size_t)r * 1024 + c0];
#pragma unroll
            for (int i = 0; i < 16; i++) dst[i] = src[i];
            return;
        }
    }
    hgemm_core<1>(ash, asl, g_wh + (size_t)3 * E_ * E_, g_wl + (size_t)3 * E_ * E_,
                  C, nullptr, nullptr, bias, qn, qlen,
                  row0, col0, smem_u32(smb));
}

// ---------------- V^T ----------------
__global__ __launch_bounds__(256) void vtrans_kernel(const __nv_bfloat16* __restrict__ vh,
                                                     const __nv_bfloat16* __restrict__ vl,
                                                     __nv_bfloat16* __restrict__ vth,
                                                     __nv_bfloat16* __restrict__ vtl) {
    __shared__ __nv_bfloat16 sm[2][64 * 66];
    const int tt = blockIdx.x;
    const int h  = blockIdx.y;
    const int b  = blockIdx.z;
    const int tid = threadIdx.x;

    const size_t in_off = ((size_t)(b * 1024 + h * 64 + tt * 4)) * 1024;
    const __nv_bfloat16* src[2] = {vh + in_off, vl + in_off};
#pragma unroll
    for (int pl = 0; pl < 2; pl++) {
        for (int it = 0; it < 8; it++) {
            int p = tid + 256 * it;
            int i = p >> 5;
            int d = (p & 31) * 2;
            *(uint32_t*)&sm[pl][i * 66 + d] = *(const uint32_t*)(src[pl] + (size_t)i * 64 + d);
        }
    }
    __syncthreads();
    const size_t out_off = ((size_t)((b * 16 + h) * 64)) * 1024 + tt * 64;
    __nv_bfloat16* dst[2] = {vth + out_off, vtl + out_off};
#pragma unroll
    for (int pl = 0; pl < 2; pl++) {
        for (int it = 0; it < 8; it++) {
            int w = tid + 256 * it;
            int d = w >> 5;
            int j = (w & 31) * 2;
            *(uint32_t*)(dst[pl] + (size_t)d * 1024 + j) = pack_bf2(sm[pl][j * 66 + d], sm[pl][(j + 1) * 66 + d]);
        }
    }
}

// ---------------- fused attention ----------------
#define EPAD 1048
static constexpr int A_SQH = 0;
static constexpr int A_SQL = 2304;
static constexpr int A_SK  = 4608;
static constexpr int A_SEH = 41472;
static constexpr int A_SEL = 75008;
static constexpr int ATTN_SMEM = 217088 + 256;

__global__ __launch_bounds__(256) void attn3_kernel(const __nv_bfloat16* __restrict__ qh,
                                                    const __nv_bfloat16* __restrict__ ql,
                                                    const __nv_bfloat16* __restrict__ kh,
                                                    const __nv_bfloat16* __restrict__ kl_,
                                                    const __nv_bfloat16* __restrict__ vth,
                                                    const __nv_bfloat16* __restrict__ vtl,
                                                    const int* __restrict__ klen,
                                                    float* __restrict__ attn_out,
                                                    __nv_bfloat16* __restrict__ ctx_h,
                                                    __nv_bfloat16* __restrict__ ctx_l) {
    extern __shared__ __nv_bfloat16 smb[];
    const uint32_t sb = smem_u32(smb);
    float* sZ = (float*)((char*)smb + 217088);

    const int b = blockIdx.z;
    const int h = blockIdx.y;
    const int q0 = blockIdx.x * 32;
    const int tid = threadIdx.x;
    const int wid = tid >> 5, lane = tid & 31;
    const int kl = klen[b];
    const int nact = (kl + 127) >> 7;

    const size_t base = (size_t)b * (S_ * E_);

    // Q load
    {
        int row = tid >> 3, seg = (tid & 7) * 8;
        int s = q0 + row;
        size_t ga = base + (size_t)((h << 6) + (s >> 4)) * 1024 + ((s & 15) << 6) + seg;
        cp_async16(sb + (uint32_t)(A_SQH + row * 72 + seg) * 2, qh + ga);
        cp_async16(sb + (uint32_t)(A_SQL + row * 72 + seg) * 2, ql + ga);
    }

    auto load_k = [&](int ch, int buf) {
        uint32_t kb = sb + (uint32_t)(A_SK + buf * 18432) * 2;
#pragma unroll
        for (int i = 0; i < 4; i++) {
            int idx = tid + i * 256;
            int j = idx >> 3, seg = (idx & 7) * 8;
            int t = ch * 128 + j;
            size_t ga = base + (size_t)((h << 6) + (t >> 4)) * 1024 + ((t & 15) << 6) + seg;
            uint32_t sa = kb + (uint32_t)(j * 72 + seg) * 2;
            cp_async16(sa, kh + ga);
            cp_async16(sa + 9216 * 2, kl_ + ga);
        }
    };
    auto load_v = [&](int ch, int buf) {
        uint32_t vb = sb + (uint32_t)(A_SK + buf * 18432) * 2;
        size_t vbase = ((size_t)((b * 16 + h) * 64)) * 1024 + ch * 128;
#pragma unroll
        for (int i = 0; i < 4; i++) {
            int idx = tid + i * 256;
            int d = idx >> 4, seg = (idx & 15) * 8;
            size_t ga = vbase + (size_t)d * 1024 + seg;
            uint32_t sa = vb + (uint32_t)(d * 136 + seg) * 2;
            cp_async16(sa, vth + ga);
            cp_async16(sa + 9216 * 2, vtl + ga);
        }
    };

    load_k(0, 0);
    cp_commit();

    // fill masked sE region; init sZ with analytic masked contribution
    {
        if (tid < 32) sZ[tid] = (float)(1024 - nact * 128);
        int t0 = nact * 128;
        int npairs = (1024 - t0) >> 1;
        if (npairs > 0) {
            uint32_t onepair = pack_bf2(__float2bfloat16_rn(1.f), __float2bfloat16_rn(1.f));
            for (int idx = tid; idx < 32 * npairs; idx += 256) {
                int r = idx / npairs;
                int p = idx - r * npairs;
                int t = t0 + p * 2;
                *(uint32_t*)&smb[A_SEH + r * EPAD + t] = onepair;
                *(uint32_t*)&smb[A_SEL + r * EPAD + t] = 0u;
            }
        }
    }

    const int mt = wid & 1;
    const int ng = wid >> 1;

    const uint32_t qa_off = (uint32_t)((mt * 16 + (lane & 15)) * 72 + (lane >> 4) * 8);
    const uint32_t kb_off = (uint32_t)((ng * 32 + (lane >> 4) * 8 + (lane & 7)) * 72 + ((lane >> 3) & 1) * 8);

    float zp0 = 0.f, zp1 = 0.f;

    // QK chunks
    for (int ch = 0; ch < nact; ch++) {
        cp_wait<0>();
        __syncthreads();
        if (ch + 1 < nact) { load_k(ch + 1, (ch + 1) & 1); cp_commit(); }

        const uint32_t Kb = sb + (uint32_t)(A_SK + (ch & 1) * 18432) * 2;
        float acc[4][4];
#pragma unroll
        for (int j = 0; j < 4; j++)
#pragma unroll
            for (int k = 0; k < 4; k++) acc[j][k] = 0.f;

#pragma unroll
        for (int ks = 0; ks < 4; ks++) {
            uint32_t a_h[4], a_l[4];
            uint32_t aoff = (qa_off + ks * 16) * 2;
            ldmx4(a_h, sb + A_SQH * 2 + aoff);
            ldmx4(a_l, sb + A_SQL * 2 + aoff);
            uint32_t b_h[2][4], b_l[2][4];
#pragma unroll
            for (int np = 0; np < 2; np++) {
                uint32_t boff = (kb_off + np * 16 * 72 + ks * 16) * 2;
                ldmx4(b_h[np], Kb + boff);
                ldmx4(b_l[np], Kb + 9216 * 2 + boff);
            }
            mma16816(acc[0], a_h, b_h[0] + 0);
            mma16816(acc[1], a_h, b_h[0] + 2);
            mma16816(acc[2], a_h, b_h[1] + 0);
            mma16816(acc[3], a_h, b_h[1] + 2);
            mma16816(acc[0], a_h, b_l[0] + 0);
            mma16816(acc[1], a_h, b_l[0] + 2);
            mma16816(acc[2], a_h, b_l[1] + 0);
            mma16816(acc[3], a_h, b_l[1] + 2);
            mma16816(acc[0], a_l, b_h[0] + 0);
            mma16816(acc[1], a_l, b_h[0] + 2);
            mma16816(acc[2], a_l, b_h[1] + 0);
            mma16816(acc[3], a_l, b_h[1] + 2);
        }

        int r1 = mt * 16 + (lane >> 2);
#pragma unroll
        for (int j = 0; j < 4; j++) {
            int c = ch * 128 + ng * 32 + j * 8 + (lane & 3) * 2;
#pragma unroll
            for (int half = 0; half < 2; half++) {
                int r = r1 + half * 8;
                float e0 = (c < kl)     ? __expf(acc[j][half * 2 + 0] * 0.125f) : 1.f;
                float e1 = (c + 1 < kl) ? __expf(acc[j][half * 2 + 1] * 0.125f) : 1.f;
                if (half == 0) zp0 += e0 + e1; else zp1 += e0 + e1;
                __nv_bfloat16 h0, h1, l0, l1;
                split1(e0, h0, l0);
                split1(e1, h1, l1);
                *(uint32_t*)&smb[A_SEH + r * EPAD + c] = pack_bf2(h0, h1);
                *(uint32_t*)&smb[A_SEL + r * EPAD + c] = pack_bf2(l0, l1);
            }
        }
    }
    cp_wait<0>();

    zp0 += __shfl_xor_sync(0xffffffffu, zp0, 1);
    zp0 += __shfl_xor_sync(0xffffffffu, zp0, 2);
    zp1 += __shfl_xor_sync(0xffffffffu, zp1, 1);
    zp1 += __shfl_xor_sync(0xffffffffu, zp1, 2);
    if ((lane & 3) == 0) {
        int r1 = mt * 16 + (lane >> 2);
        atomicAdd(&sZ[r1], zp0);
        atomicAdd(&sZ[r1 + 8], zp1);
    }
    __syncthreads();

    load_v(0, 0);
    cp_commit();
    if (tid < 32) sZ[tid] = 1.f / sZ[tid];
    __syncthreads();

    const uint32_t ea_base = (uint32_t)((mt * 16 + (lane & 15)) * EPAD + (lane >> 4) * 8);
    const uint32_t vb_off = (uint32_t)((ng * 16 + (lane >> 4) * 8 + (lane & 7)) * 136 + ((lane >> 3) & 1) * 8);

    float cacc[2][4];
#pragma unroll
    for (int j = 0; j < 2; j++)
#pragma unroll
        for (int k = 0; k < 4; k++) cacc[j][k] = 0.f;

    size_t abase = 0;
    if (attn_out) abase = (((size_t)b * H_ + h) * S_ + q0) * (size_t)S_;

    for (int ch = 0; ch < 8; ch++) {
        cp_wait<0>();
        __syncthreads();
        if (ch + 1 < 8) { load_v(ch + 1, (ch + 1) & 1); cp_commit(); }

        if (attn_out) {
#pragma unroll
            for (int rr = 0; rr < 4; rr++) {
                int r = wid * 4 + rr;
                float invZ = sZ[r];
                int t = ch * 128 + lane * 4;
                uint2 ph = *(uint2*)&smb[A_SEH + r * EPAD + t];
                uint2 pl = *(uint2*)&smb[A_SEL + r * EPAD + t];
                __nv_bfloat162 h01 = *(__nv_bfloat162*)&ph.x;
                __nv_bfloat162 h23 = *(__nv_bfloat162*)&ph.y;
                __nv_bfloat162 l01 = *(__nv_bfloat162*)&pl.x;
                __nv_bfloat162 l23 = *(__nv_bfloat162*)&pl.y;
                float4 p;
                p.x = (__bfloat162float(h01.x) + __bfloat162float(l01.x)) * invZ;
                p.y = (__bfloat162float(h01.y) + __bfloat162float(l01.y)) * invZ;
                p.z = (__bfloat162float(h23.x) + __bfloat162float(l23.x)) * invZ;
                p.w = (__bfloat162float(h23.y) + __bfloat162float(l23.y)) * invZ;
                *(float4*)&attn_out[abase + (size_t)r * S_ + t] = p;
            }
        }

        const uint32_t Vb = sb + (uint32_t)(A_SK + (ch & 1) * 18432) * 2;
#pragma unroll
        for (int ks = 0; ks < 8; ks++) {
            uint32_t a_h[4], a_l[4];
            uint32_t aoff = (ea_base + ch * 128 + ks * 16) * 2;
            ldmx4(a_h, sb + A_SEH * 2 + aoff);
            ldmx4(a_l, sb + A_SEL * 2 + aoff);
            uint32_t b_h[4], b_l[4];
            uint32_t boff = (vb_off + ks * 16) * 2;
            ldmx4(b_h, Vb + boff);
            ldmx4(b_l, Vb + 9216 * 2 + boff);
            mma16816(cacc[0], a_h, b_h + 0);
            mma16816(cacc[0], a_h, b_l + 0);
            mma16816(cacc[0], a_l, b_h + 0);
            mma16816(cacc[1], a_h, b_h + 2);
            mma16816(cacc[1], a_h, b_l + 2);
            mma16816(cacc[1], a_l, b_h + 2);
        }
    }

    // ctx write
    {
        int r1 = mt * 16 + (lane >> 2);
#pragma unroll
        for (int j = 0; j < 2; j++) {
            int c = ng * 16 + j * 8 + (lane & 3) * 2;
#pragma unroll
            for (int half = 0; half < 2; half++) {
                int r = r1 + half * 8;
                float invZ = sZ[r];
                float v0 = cacc[j][half * 2 + 0] * invZ;
                float v1 = cacc[j][half * 2 + 1] * invZ;
                __nv_bfloat16 h0, h1, l0, l1;
                split1(v0, h0, l0);
                split1(v1, h1, l1);
                size_t oa = (size_t)(b * 1024 + q0 + r) * 1024 + (h << 6) + c;
                *(uint32_t*)&ctx_h[oa] = pack_bf2(h0, h1);
                *(uint32_t*)&ctx_l[oa] = pack_bf2(l0, l1);
            }
        }
    }
}

// ---------------- launcher ----------------
extern "C" void kernel_launch(void* const* d_in, const int* in_sizes, int n_in,
                              void* d_out, int out_size) {
    const float* query = (const float*)d_in[0];
    const float* key   = (const float*)d_in[1];
    const float* value = (const float*)d_in[2];
    const int*   qlen  = (const int*)d_in[3];
    const int*   klen  = (const int*)d_in[4];
    const float* wq    = (const float*)d_in[5];
    const float* wk    = (const float*)d_in[6];
    const float* wv    = (const float*)d_in[7];
    const float* gamma = (const float*)d_in[8];
    const float* beta  = (const float*)d_in[9];
    const float* outw  = (const float*)d_in[10];
    const float* outb  = (const float*)d_in[11];

    float* out = (float*)d_out;
    const long long n_skip = (long long)B_ * S_ * E_;
    const long long n_attn = (long long)B_ * H_ * S_ * (long long)S_;
    float* attn_out = ((long long)out_size >= n_skip + n_attn) ? (out + n_skip) : nullptr;

    float* qn;
    __nv_bfloat16 *ash, *asl, *qh, *ql, *kh, *kl_, *vh, *vl, *vth, *vtl, *wh, *wl;
    cudaGetSymbolAddress((void**)&qn,  g_qn);
    cudaGetSymbolAddress((void**)&ash, g_ash);
    cudaGetSymbolAddress((void**)&asl, g_asl);
    cudaGetSymbolAddress((void**)&qh,  g_qh);
    cudaGetSymbolAddress((void**)&ql,  g_ql);
    cudaGetSymbolAddress((void**)&kh,  g_kh);
    cudaGetSymbolAddress((void**)&kl_, g_kl);
    cudaGetSymbolAddress((void**)&vh,  g_vh);
    cudaGetSymbolAddress((void**)&vl,  g_vl);
    cudaGetSymbolAddress((void**)&vth, g_vth);
    cudaGetSymbolAddress((void**)&vtl, g_vtl);
    cudaGetSymbolAddress((void**)&wh,  g_wh);
    cudaGetSymbolAddress((void**)&wl,  g_wl);

    // allow 2 CTAs/SM: max smem carveout + per-block dynamic smem limit
    cudaFuncSetAttribute(hgemm_proj, cudaFuncAttributeMaxDynamicSharedMemorySize, GEMM_SMEM);
    cudaFuncSetAttribute(hgemm_out,  cudaFuncAttributeMaxDynamicSharedMemorySize, GEMM_SMEM);
    cudaFuncSetAttribute(hgemm_proj, cudaFuncAttributePreferredSharedMemoryCarveout, 100);
    cudaFuncSetAttribute(hgemm_out,  cudaFuncAttributePreferredSharedMemoryCarveout, 100);
    cudaFuncSetAttribute(attn3_kernel, cudaFuncAttributeMaxDynamicSharedMemorySize, ATTN_SMEM);
    cudaFuncSetAttribute(attn3_kernel, cudaFuncAttributePreferredSharedMemoryCarveout, 100);

    const size_t NSE = (size_t)B_ * S_ * E_;
    const size_t NEE = (size_t)E_ * E_;

    ln_split_kernel<<<B_ * S_, 256>>>(query, gamma, beta, qn, ash, asl);

    dim3 sgrid(B_ * S_ * E_ / 4 / 256, 2);
    split2_kernel<<<sgrid, 256>>>(key, value, ash, asl);

    dim3 tgrid(32, 32, 4);
    tsplit4_kernel<<<tgrid, 256>>>(wq, wk, wv, outw);

    dim3 ggrid(8, 32);
    hgemm_proj<<<ggrid, 256, GEMM_SMEM>>>(ash,           asl,           wh,           wl,           qh, ql);
    hgemm_proj<<<ggrid, 256, GEMM_SMEM>>>(ash + NSE,     asl + NSE,     wh + NEE,     wl + NEE,     kh, kl_);
    hgemm_proj<<<ggrid, 256, GEMM_SMEM>>>(ash + 2 * NSE, asl + 2 * NSE, wh + 2 * NEE, wl + 2 * NEE, vh, vl);

    dim3 vgrid(16, H_, B_);
    vtrans_kernel<<<vgrid, 256>>>(vh, vl, vth, vtl);

    dim3 agrid(S_ / 32, H_, B_);
    attn3_kernel<<<agrid, 256, ATTN_SMEM>>>(qh, ql, kh, kl_, vth, vtl, klen, attn_out, ash, asl);

    hgemm_out<<<ggrid, 256, GEMM_SMEM>>>(ash, asl, out, outb, qn, qlen);
}

// round 16
// speedup vs baseline: 1.0240x; 1.0240x over previous
#include <cuda_runtime.h>
#include <cuda_bf16.h>
#include <math.h>
#include <stdint.h>

#define B_    4
#define S_    1024
#define E_    1024
#define H_    16
#define DH_   64

// ---------------- scratch ----------------
__device__ float g_qn [B_ * S_ * E_];
__device__ __nv_bfloat16 g_ash[3 * B_ * S_ * E_];
__device__ __nv_bfloat16 g_asl[3 * B_ * S_ * E_];
__device__ __nv_bfloat16 g_wh[4 * E_ * E_];
__device__ __nv_bfloat16 g_wl[4 * E_ * E_];
__device__ __nv_bfloat16 g_qh[B_ * S_ * E_];
__device__ __nv_bfloat16 g_ql[B_ * S_ * E_];
__device__ __nv_bfloat16 g_kh[B_ * S_ * E_];
__device__ __nv_bfloat16 g_kl[B_ * S_ * E_];
__device__ __nv_bfloat16 g_vh[B_ * S_ * E_];
__device__ __nv_bfloat16 g_vl[B_ * S_ * E_];

// ---------------- PTX helpers ----------------
__device__ __forceinline__ uint32_t smem_u32(const void* p) {
    uint32_t a;
    asm("{ .reg .u64 t; cvta.to.shared.u64 t, %1; cvt.u32.u64 %0, t; }" : "=r"(a) : "l"(p));
    return a;
}
__device__ __forceinline__ void cp_async16(uint32_t s, const void* g) {
    asm volatile("cp.async.cg.shared.global [%0], [%1], 16;" :: "r"(s), "l"(g));
}
__device__ __forceinline__ void cp_commit() { asm volatile("cp.async.commit_group;" ::: "memory"); }
template<int N> __device__ __forceinline__ void cp_wait() { asm volatile("cp.async.wait_group %0;" :: "n"(N) : "memory"); }

__device__ __forceinline__ void ldmx4(uint32_t* r, uint32_t addr) {
    asm volatile("ldmatrix.sync.aligned.m8n8.x4.shared.b16 {%0,%1,%2,%3}, [%4];"
        : "=r"(r[0]), "=r"(r[1]), "=r"(r[2]), "=r"(r[3]) : "r"(addr));
}
__device__ __forceinline__ void ldmx4t(uint32_t* r, uint32_t addr) {
    asm volatile("ldmatrix.sync.aligned.m8n8.x4.trans.shared.b16 {%0,%1,%2,%3}, [%4];"
        : "=r"(r[0]), "=r"(r[1]), "=r"(r[2]), "=r"(r[3]) : "r"(addr));
}
__device__ __forceinline__ void mma16816(float* d, const uint32_t* a, const uint32_t* b) {
    asm volatile("mma.sync.aligned.m16n8k16.row.col.f32.bf16.bf16.f32 "
        "{%0,%1,%2,%3}, {%4,%5,%6,%7}, {%8,%9}, {%0,%1,%2,%3};"
        : "+f"(d[0]), "+f"(d[1]), "+f"(d[2]), "+f"(d[3])
        : "r"(a[0]), "r"(a[1]), "r"(a[2]), "r"(a[3]), "r"(b[0]), "r"(b[1]));
}
__device__ __forceinline__ uint32_t pack_bf2(__nv_bfloat16 a, __nv_bfloat16 b) {
    uint16_t ua = *(uint16_t*)&a, ub = *(uint16_t*)&b;
    return (uint32_t)ua | ((uint32_t)ub << 16);
}
__device__ __forceinline__ void split1(float v, __nv_bfloat16& h, __nv_bfloat16& l) {
    h = __float2bfloat16_rn(v);
    l = __float2bfloat16_rn(v - __bfloat162float(h));
}

// ---------------- layernorm + Q split ----------------
__global__ __launch_bounds__(256) void ln_split_kernel(const float* __restrict__ x,
                                                       const float* __restrict__ gamma,
                                                       const float* __restrict__ beta,
                                                       float* __restrict__ y,
                                                       __nv_bfloat16* __restrict__ sh,
                                                       __nv_bfloat16* __restrict__ sl) {
    __shared__ float red[32];
    int row = blockIdx.x;
    int tid = threadIdx.x;
    const float* xr = x + (size_t)row * 1024;

    float v[4];
    float s = 0.f;
#pragma unroll
    for (int i = 0; i < 4; i++) { v[i] = xr[tid + 256 * i]; s += v[i]; }

    for (int off = 16; off; off >>= 1) s += __shfl_xor_sync(0xffffffffu, s, off);
    int lane = tid & 31, wid = tid >> 5;
    if (lane == 0) red[wid] = s;
    __syncthreads();
    if (wid == 0) {
        float t = (lane < 8) ? red[lane] : 0.f;
        for (int off = 4; off; off >>= 1) t += __shfl_xor_sync(0xffffffffu, t, off);
        if (lane == 0) red[0] = t;
    }
    __syncthreads();
    float mean = red[0] * (1.f / 1024.f);
    __syncthreads();

    float vs = 0.f;
#pragma unroll
    for (int i = 0; i < 4; i++) { float d = v[i] - mean; vs += d * d; }
    for (int off = 16; off; off >>= 1) vs += __shfl_xor_sync(0xffffffffu, vs, off);
    if (lane == 0) red[wid] = vs;
    __syncthreads();
    if (wid == 0) {
        float t = (lane < 8) ? red[lane] : 0.f;
        for (int off = 4; off; off >>= 1) t += __shfl_xor_sync(0xffffffffu, t, off);
        if (lane == 0) red[0] = t;
    }
    __syncthreads();
    float var = red[0] * (1.f / 1024.f);
    float rstd = rsqrtf(var + 1e-5f);

    float* yr = y + (size_t)row * 1024;
#pragma unroll
    for (int i = 0; i < 4; i++) {
        int c = tid + 256 * i;
        float o = (v[i] - mean) * rstd * gamma[c] + beta[c];
        yr[c] = o;
        __nv_bfloat16 hh, ll;
        split1(o, hh, ll);
        sh[(size_t)row * 1024 + c] = hh;
        sl[(size_t)row * 1024 + c] = ll;
    }
}

// ---------------- batched fp32 -> bf16 split (key, value) ----------------
__global__ __launch_bounds__(256) void split2_kernel(const float* __restrict__ key,
                                                     const float* __restrict__ value,
                                                     __nv_bfloat16* __restrict__ hi,
                                                     __nv_bfloat16* __restrict__ lo) {
    const float* x = blockIdx.y ? value : key;
    size_t slot = (size_t)(blockIdx.y + 1) * (B_ * S_ * E_);
    int i = blockIdx.x * 256 + threadIdx.x;
    float4 v = *(const float4*)(x + (size_t)i * 4);
    float f[4] = {v.x, v.y, v.z, v.w};
    __nv_bfloat16 h[4], l[4];
#pragma unroll
    for (int j = 0; j < 4; j++) split1(f[j], h[j], l[j]);
    *(uint2*)(hi + slot + (size_t)i * 4) = *(uint2*)h;
    *(uint2*)(lo + slot + (size_t)i * 4) = *(uint2*)l;
}

// ---------------- batched W -> W^T split ----------------
__global__ __launch_bounds__(256) void tsplit4_kernel(const float* __restrict__ w0,
                                                      const float* __restrict__ w1,
                                                      const float* __restrict__ w2,
                                                      const float* __restrict__ w3) {
    __shared__ float t[32][33];
    const float* W = (blockIdx.z == 0) ? w0 : (blockIdx.z == 1) ? w1 : (blockIdx.z == 2) ? w2 : w3;
    size_t slot = (size_t)blockIdx.z * (E_ * E_);
    int bx = blockIdx.x * 32;
    int by = blockIdx.y * 32;
    int x = threadIdx.x & 31, y = threadIdx.x >> 5;
#pragma unroll
    for (int i = 0; i < 32; i += 8)
        t[y + i][x] = W[(size_t)(by + y + i) * 1024 + bx + x];
    __syncthreads();
#pragma unroll
    for (int i = 0; i < 32; i += 8) {
        int n = bx + y + i, k = by + x;
        __nv_bfloat16 h, l;
        split1(t[x][y + i], h, l);
        g_wh[slot + (size_t)n * 1024 + k] = h;
        g_wl[slot + (size_t)n * 1024 + k] = l;
    }
}

// ---------------- HMMA bf16x3 GEMM core ----------------
#define LDK 40
static constexpr int MAT_H  = 128 * LDK;
static constexpr int GEMM_SMEM = 2 * 4 * MAT_H * 2;

template<int MODE>
__device__ __forceinline__ void hgemm_core(const __nv_bfloat16* Ah, const __nv_bfloat16* Al,
                                           const __nv_bfloat16* Bth, const __nv_bfloat16* Btl,
                                           float* C, __nv_bfloat16* Oh, __nv_bfloat16* Ol,
                                           const float* bias, const float* qn, const int* qlen,
                                           int row0, int col0, uint32_t sbase) {
    const int tid = threadIdx.x;
    const int wid = tid >> 5, lane = tid & 31;

    const __nv_bfloat16* gp0 = Ah  + (size_t)row0 * 1024;
    const __nv_bfloat16* gp1 = Al  + (size_t)row0 * 1024;
    const __nv_bfloat16* gp2 = Bth + (size_t)col0 * 1024;
    const __nv_bfloat16* gp3 = Btl + (size_t)col0 * 1024;

    const int lr = tid >> 2;
    const int lq = (tid & 3) * 8;

    auto load_stage = [&](int st, int kt) {
        uint32_t sb = sbase + (uint32_t)st * 4 * MAT_H * 2;
        const __nv_bfloat16* gs[4] = {gp0 + kt * 32, gp1 + kt * 32, gp2 + kt * 32, gp3 + kt * 32};
#pragma unroll
        for (int m = 0; m < 4; m++) {
#pragma unroll
            for (int i = 0; i < 2; i++) {
                int r = lr + i * 64;
                cp_async16(sb + (uint32_t)(m * MAT_H + r * LDK + lq) * 2,
                           gs[m] + (size_t)r * 1024 + lq);
            }
        }
    };

    load_stage(0, 0);
    cp_commit();

    float acc[2][8][4];
#pragma unroll
    for (int mt = 0; mt < 2; mt++)
#pragma unroll
        for (int nt = 0; nt < 8; nt++)
#pragma unroll
            for (int j = 0; j < 4; j++) acc[mt][nt][j] = 0.f;

    const int warp_m = (wid & 3) * 32;
    const int warp_n = (wid >> 2) * 64;

    const uint32_t a_off = (uint32_t)((warp_m + (lane & 15)) * LDK + (lane >> 4) * 8);
    const uint32_t b_off = (uint32_t)((warp_n + (lane >> 4) * 8 + (lane & 7)) * LDK + ((lane >> 3) & 1) * 8);

    for (int kt = 0; kt < 32; kt++) {
        const int st = kt & 1;
        if (kt + 1 < 32) {
            load_stage(st ^ 1, kt + 1);
            cp_commit();
            cp_wait<1>();
        } else {
            cp_wait<0>();
        }
        __syncthreads();

        const uint32_t Abase = sbase + (uint32_t)st * 4 * MAT_H * 2;
        const uint32_t Bbase = Abase + 2 * MAT_H * 2;
#pragma unroll
        for (int ks = 0; ks < 2; ks++) {
            const uint32_t kadd = (uint32_t)(ks * 16) * 2;
            uint32_t a_h[2][4], a_l[2][4];
#pragma unroll
            for (int mt = 0; mt < 2; mt++) {
                uint32_t off = (a_off + (uint32_t)(mt * 16) * LDK) * 2 + kadd;
                ldmx4(a_h[mt], Abase + off);
                ldmx4(a_l[mt], Abase + MAT_H * 2 + off);
            }
#pragma unroll
            for (int np = 0; np < 4; np++) {
                uint32_t b_h[4], b_l[4];
                uint32_t off = (b_off + (uint32_t)(np * 16) * LDK) * 2 + kadd;
                ldmx4(b_h, Bbase + off);
                ldmx4(b_l, Bbase + MAT_H * 2 + off);
#pragma unroll
                for (int mt = 0; mt < 2; mt++) {
                    mma16816(acc[mt][np * 2 + 0], a_h[mt], b_h + 0);
                    mma16816(acc[mt][np * 2 + 0], a_h[mt], b_l + 0);
                    mma16816(acc[mt][np * 2 + 0], a_l[mt], b_h + 0);
                    mma16816(acc[mt][np * 2 + 1], a_h[mt], b_h + 2);
                    mma16816(acc[mt][np * 2 + 1], a_h[mt], b_l + 2);
                    mma16816(acc[mt][np * 2 + 1], a_l[mt], b_h + 2);
                }
            }
        }
        __syncthreads();
    }

#pragma unroll
    for (int mt = 0; mt < 2; mt++) {
        int r0i = row0 + warp_m + mt * 16 + (lane >> 2);
#pragma unroll
        for (int half = 0; half < 2; half++) {
            int r = r0i + half * 8;
            float keep = 1.f;
            if (MODE == 1) {
                int bb = r >> 10, ss = r & 1023;
                keep = (ss < qlen[bb]) ? 1.f : 0.f;
            }
#pragma unroll
            for (int nt = 0; nt < 8; nt++) {
                int c = col0 + warp_n + nt * 8 + (lane & 3) * 2;
                float v0 = acc[mt][nt][half * 2 + 0];
                float v1 = acc[mt][nt][half * 2 + 1];
                if (MODE == 1) {
                    const float2 bi = *(const float2*)&bias[c];
                    const float2 q2 = *(const float2*)&qn[(size_t)r * 1024 + c];
                    v0 = (v0 + bi.x) * keep + q2.x;
                    v1 = (v1 + bi.y) * keep + q2.y;
                    *(float2*)&C[(size_t)r * 1024 + c] = make_float2(v0, v1);
                } else {
                    __nv_bfloat16 h0, h1, l0, l1;
                    split1(v0, h0, l0);
                    split1(v1, h1, l1);
                    *(uint32_t*)&Oh[(size_t)r * 1024 + c] = pack_bf2(h0, h1);
                    *(uint32_t*)&Ol[(size_t)r * 1024 + c] = pack_bf2(l0, l1);
                }
            }
        }
    }
}

__global__ __launch_bounds__(256) void hgemm_proj(const __nv_bfloat16* __restrict__ ash,
                                                  const __nv_bfloat16* __restrict__ asl,
                                                  const __nv_bfloat16* __restrict__ wth,
                                                  const __nv_bfloat16* __restrict__ wtl,
                                                  __nv_bfloat16* __restrict__ oh,
                                                  __nv_bfloat16* __restrict__ ol) {
    extern __shared__ __nv_bfloat16 smb[];
    hgemm_core<0>(ash, asl, wth, wtl, nullptr, oh, ol, nullptr, nullptr, nullptr,
                  blockIdx.y * 128, blockIdx.x * 128, smem_u32(smb));
}

__global__ __launch_bounds__(256) void hgemm_out(const __nv_bfloat16* __restrict__ ash,
                                                 const __nv_bfloat16* __restrict__ asl,
                                                 float* __restrict__ C,
                                                 const float* __restrict__ bias,
                                                 const float* __restrict__ qn,
                                                 const int* __restrict__ qlen) {
    extern __shared__ __nv_bfloat16 smb[];
    int row0 = blockIdx.y * 128;
    int col0 = blockIdx.x * 128;
    {
        int bb = row0 >> 10, ss = row0 & 1023;
        if (ss >= qlen[bb]) {
            int tid = threadIdx.x;
            int r = row0 + (tid >> 1);
            int c0 = col0 + (tid & 1) * 64;
            const float4* src = (const float4*)&qn[(size_t)r * 1024 + c0];
            float4* dst = (float4*)&C[(size_t)r * 1024 + c0];
#pragma unroll
            for (int i = 0; i < 16; i++) dst[i] = src[i];
            return;
        }
    }
    hgemm_core<1>(ash, asl, g_wh + (size_t)3 * E_ * E_, g_wl + (size_t)3 * E_ * E_,
                  C, nullptr, nullptr, bias, qn, qlen,
                  row0, col0, smem_u32(smb));
}

// ---------------- fused attention: V loaded K-style, transposed via ldmatrix.trans ----------------
#define EPAD 1048
static constexpr int A_SQH = 0;
static constexpr int A_SQL = 2304;
static constexpr int A_SK  = 4608;
static constexpr int A_SEH = 41472;
static constexpr int A_SEL = 75008;
static constexpr int ATTN_SMEM = 217088 + 256;

__global__ __launch_bounds__(256) void attn3_kernel(const __nv_bfloat16* __restrict__ qh,
                                                    const __nv_bfloat16* __restrict__ ql,
                                                    const __nv_bfloat16* __restrict__ kh,
                                                    const __nv_bfloat16* __restrict__ kl_,
                                                    const __nv_bfloat16* __restrict__ vh,
                                                    const __nv_bfloat16* __restrict__ vl,
                                                    const int* __restrict__ klen,
                                                    float* __restrict__ attn_out,
                                                    __nv_bfloat16* __restrict__ ctx_h,
                                                    __nv_bfloat16* __restrict__ ctx_l) {
    extern __shared__ __nv_bfloat16 smb[];
    const uint32_t sb = smem_u32(smb);
    float* sZ = (float*)((char*)smb + 217088);

    const int b = blockIdx.z;
    const int h = blockIdx.y;
    const int q0 = blockIdx.x * 32;
    const int tid = threadIdx.x;
    const int wid = tid >> 5, lane = tid & 31;
    const int kl = klen[b];
    const int nact = (kl + 127) >> 7;

    const size_t base = (size_t)b * (S_ * E_);

    // Q load
    {
        int row = tid >> 3, seg = (tid & 7) * 8;
        int s = q0 + row;
        size_t ga = base + (size_t)((h << 6) + (s >> 4)) * 1024 + ((s & 15) << 6) + seg;
        cp_async16(sb + (uint32_t)(A_SQH + row * 72 + seg) * 2, qh + ga);
        cp_async16(sb + (uint32_t)(A_SQL + row * 72 + seg) * 2, ql + ga);
    }

    // K-style chunk loader (used for both K and V: same non-standard layout)
    auto load_kv = [&](const __nv_bfloat16* ph, const __nv_bfloat16* pl, int ch, int buf) {
        uint32_t kb = sb + (uint32_t)(A_SK + buf * 18432) * 2;
#pragma unroll
        for (int i = 0; i < 4; i++) {
            int idx = tid + i * 256;
            int j = idx >> 3, seg = (idx & 7) * 8;
            int t = ch * 128 + j;
            size_t ga = base + (size_t)((h << 6) + (t >> 4)) * 1024 + ((t & 15) << 6) + seg;
            uint32_t sa = kb + (uint32_t)(j * 72 + seg) * 2;
            cp_async16(sa, ph + ga);
            cp_async16(sa + 9216 * 2, pl + ga);
        }
    };

    load_kv(kh, kl_, 0, 0);
    cp_commit();

    // fill masked sE region; init sZ with analytic masked contribution
    {
        if (tid < 32) sZ[tid] = (float)(1024 - nact * 128);
        int t0 = nact * 128;
        int npairs = (1024 - t0) >> 1;
        if (npairs > 0) {
            uint32_t onepair = pack_bf2(__float2bfloat16_rn(1.f), __float2bfloat16_rn(1.f));
            for (int idx = tid; idx < 32 * npairs; idx += 256) {
                int r = idx / npairs;
                int p = idx - r * npairs;
                int t = t0 + p * 2;
                *(uint32_t*)&smb[A_SEH + r * EPAD + t] = onepair;
                *(uint32_t*)&smb[A_SEL + r * EPAD + t] = 0u;
            }
        }
    }

    const int mt = wid & 1;
    const int ng = wid >> 1;

    const uint32_t qa_off = (uint32_t)((mt * 16 + (lane & 15)) * 72 + (lane >> 4) * 8);
    const uint32_t kb_off = (uint32_t)((ng * 32 + (lane >> 4) * 8 + (lane & 7)) * 72 + ((lane >> 3) & 1) * 8);

    float zp0 = 0.f, zp1 = 0.f;

    // QK chunks
    for (int ch = 0; ch < nact; ch++) {
        cp_wait<0>();
        __syncthreads();
        if (ch + 1 < nact) { load_kv(kh, kl_, ch + 1, (ch + 1) & 1); cp_commit(); }

        const uint32_t Kb = sb + (uint32_t)(A_SK + (ch & 1) * 18432) * 2;
        float acc[4][4];
#pragma unroll
        for (int j = 0; j < 4; j++)
#pragma unroll
            for (int k = 0; k < 4; k++) acc[j][k] = 0.f;

#pragma unroll
        for (int ks = 0; ks < 4; ks++) {
            uint32_t a_h[4], a_l[4];
            uint32_t aoff = (qa_off + ks * 16) * 2;
            ldmx4(a_h, sb + A_SQH * 2 + aoff);
            ldmx4(a_l, sb + A_SQL * 2 + aoff);
            uint32_t b_h[2][4], b_l[2][4];
#pragma unroll
            for (int np = 0; np < 2; np++) {
                uint32_t boff = (kb_off + np * 16 * 72 + ks * 16) * 2;
                ldmx4(b_h[np], Kb + boff);
                ldmx4(b_l[np], Kb + 9216 * 2 + boff);
            }
            mma16816(acc[0], a_h, b_h[0] + 0);
            mma16816(acc[1], a_h, b_h[0] + 2);
            mma16816(acc[2], a_h, b_h[1] + 0);
            mma16816(acc[3], a_h, b_h[1] + 2);
            mma16816(acc[0], a_h, b_l[0] + 0);
            mma16816(acc[1], a_h, b_l[0] + 2);
            mma16816(acc[2], a_h, b_l[1] + 0);
            mma16816(acc[3], a_h, b_l[1] + 2);
            mma16816(acc[0], a_l, b_h[0] + 0);
            mma16816(acc[1], a_l, b_h[0] + 2);
            mma16816(acc[2], a_l, b_h[1] + 0);
            mma16816(acc[3], a_l, b_h[1] + 2);
        }

        int r1 = mt * 16 + (lane >> 2);
#pragma unroll
        for (int j = 0; j < 4; j++) {
            int c = ch * 128 + ng * 32 + j * 8 + (lane & 3) * 2;
#pragma unroll
            for (int half = 0; half < 2; half++) {
                int r = r1 + half * 8;
                float e0 = (c < kl)     ? __expf(acc[j][half * 2 + 0] * 0.125f) : 1.f;
                float e1 = (c + 1 < kl) ? __expf(acc[j][half * 2 + 1] * 0.125f) : 1.f;
                if (half == 0) zp0 += e0 + e1; else zp1 += e0 + e1;
                __nv_bfloat16 h0, h1, l0, l1;
                split1(e0, h0, l0);
                split1(e1, h1, l1);
                *(uint32_t*)&smb[A_SEH + r * EPAD + c] = pack_bf2(h0, h1);
                *(uint32_t*)&smb[A_SEL + r * EPAD + c] = pack_bf2(l0, l1);
            }
        }
    }
    cp_wait<0>();

    zp0 += __shfl_xor_sync(0xffffffffu, zp0, 1);
    zp0 += __shfl_xor_sync(0xffffffffu, zp0, 2);
    zp1 += __shfl_xor_sync(0xffffffffu, zp1, 1);
    zp1 += __shfl_xor_sync(0xffffffffu, zp1, 2);
    if ((lane & 3) == 0) {
        int r1 = mt * 16 + (lane >> 2);
        atomicAdd(&sZ[r1], zp0);
        atomicAdd(&sZ[r1 + 8], zp1);
    }
    __syncthreads();

    load_kv(vh, vl, 0, 0);
    cp_commit();
    if (tid < 32) sZ[tid] = 1.f / sZ[tid];
    __syncthreads();

    // PV: E fragments as before; V fragments via ldmatrix.trans from [t][d] tiles.
    const uint32_t ea_base = (uint32_t)((mt * 16 + (lane & 15)) * EPAD + (lane >> 4) * 8);
    // trans addressing: rows t = (lane&7) + ((lane>>3)&1)*8, col d = ng*16 + ((lane>>4)&1)*8
    const uint32_t vbt_off = (uint32_t)(((lane & 7) + ((lane >> 3) & 1) * 8) * 72 + ng * 16 + ((lane >> 4) & 1) * 8);

    float cacc[2][4];
#pragma unroll
    for (int j = 0; j < 2; j++)
#pragma unroll
        for (int k = 0; k < 4; k++) cacc[j][k] = 0.f;

    size_t abase = 0;
    if (attn_out) abase = (((size_t)b * H_ + h) * S_ + q0) * (size_t)S_;

    for (int ch = 0; ch < 8; ch++) {
        cp_wait<0>();
        __syncthreads();
        if (ch + 1 < 8) { load_kv(vh, vl, ch + 1, (ch + 1) & 1); cp_commit(); }

        if (attn_out) {
#pragma unroll
            for (int rr = 0; rr < 4; rr++) {
                int r = wid * 4 + rr;
                float invZ = sZ[r];
                int t = ch * 128 + lane * 4;
                uint2 ph = *(uint2*)&smb[A_SEH + r * EPAD + t];
                uint2 pl = *(uint2*)&smb[A_SEL + r * EPAD + t];
                __nv_bfloat162 h01 = *(__nv_bfloat162*)&ph.x;
                __nv_bfloat162 h23 = *(__nv_bfloat162*)&ph.y;
                __nv_bfloat162 l01 = *(__nv_bfloat162*)&pl.x;
                __nv_bfloat162 l23 = *(__nv_bfloat162*)&pl.y;
                float4 p;
                p.x = (__bfloat162float(h01.x) + __bfloat162float(l01.x)) * invZ;
                p.y = (__bfloat162float(h01.y) + __bfloat162float(l01.y)) * invZ;
                p.z = (__bfloat162float(h23.x) + __bfloat162float(l23.x)) * invZ;
                p.w = (__bfloat162float(h23.y) + __bfloat162float(l23.y)) * invZ;
                *(float4*)&attn_out[abase + (size_t)r * S_ + t] = p;
            }
        }

        const uint32_t Vb = sb + (uint32_t)(A_SK + (ch & 1) * 18432) * 2;
#pragma unroll
        for (int ks = 0; ks < 8; ks++) {
            uint32_t a_h[4], a_l[4];
            uint32_t aoff = (ea_base + ch * 128 + ks * 16) * 2;
            ldmx4(a_h, sb + A_SEH * 2 + aoff);
            ldmx4(a_l, sb + A_SEL * 2 + aoff);
            uint32_t b_h[4], b_l[4];
            uint32_t boff = (vbt_off + (uint32_t)(ks * 16) * 72) * 2;
            ldmx4t(b_h, Vb + boff);
            ldmx4t(b_l, Vb + 9216 * 2 + boff);
            mma16816(cacc[0], a_h, b_h + 0);
            mma16816(cacc[0], a_h, b_l + 0);
            mma16816(cacc[0], a_l, b_h + 0);
            mma16816(cacc[1], a_h, b_h + 2);
            mma16816(cacc[1], a_h, b_l + 2);
            mma16816(cacc[1], a_l, b_h + 2);
        }
    }

    // ctx write
    {
        int r1 = mt * 16 + (lane >> 2);
#pragma unroll
        for (int j = 0; j < 2; j++) {
            int c = ng * 16 + j * 8 + (lane & 3) * 2;
#pragma unroll
            for (int half = 0; half < 2; half++) {
                int r = r1 + half * 8;
                float invZ = sZ[r];
                float v0 = cacc[j][half * 2 + 0] * invZ;
                float v1 = cacc[j][half * 2 + 1] * invZ;
                __nv_bfloat16 h0, h1, l0, l1;
                split1(v0, h0, l0);
                split1(v1, h1, l1);
                size_t oa = (size_t)(b * 1024 + q0 + r) * 1024 + (h << 6) + c;
                *(uint32_t*)&ctx_h[oa] = pack_bf2(h0, h1);
                *(uint32_t*)&ctx_l[oa] = pack_bf2(l0, l1);
            }
        }
    }
}

// ---------------- launcher ----------------
extern "C" void kernel_launch(void* const* d_in, const int* in_sizes, int n_in,
                              void* d_out, int out_size) {
    const float* query = (const float*)d_in[0];
    const float* key   = (const float*)d_in[1];
    const float* value = (const float*)d_in[2];
    const int*   qlen  = (const int*)d_in[3];
    const int*   klen  = (const int*)d_in[4];
    const float* wq    = (const float*)d_in[5];
    const float* wk    = (const float*)d_in[6];
    const float* wv    = (const float*)d_in[7];
    const float* gamma = (const float*)d_in[8];
    const float* beta  = (const float*)d_in[9];
    const float* outw  = (const float*)d_in[10];
    const float* outb  = (const float*)d_in[11];

    float* out = (float*)d_out;
    const long long n_skip = (long long)B_ * S_ * E_;
    const long long n_attn = (long long)B_ * H_ * S_ * (long long)S_;
    float* attn_out = ((long long)out_size >= n_skip + n_attn) ? (out + n_skip) : nullptr;

    float* qn;
    __nv_bfloat16 *ash, *asl, *qh, *ql, *kh, *kl_, *vh, *vl, *wh, *wl;
    cudaGetSymbolAddress((void**)&qn,  g_qn);
    cudaGetSymbolAddress((void**)&ash, g_ash);
    cudaGetSymbolAddress((void**)&asl, g_asl);
    cudaGetSymbolAddress((void**)&qh,  g_qh);
    cudaGetSymbolAddress((void**)&ql,  g_ql);
    cudaGetSymbolAddress((void**)&kh,  g_kh);
    cudaGetSymbolAddress((void**)&kl_, g_kl);
    cudaGetSymbolAddress((void**)&vh,  g_vh);
    cudaGetSymbolAddress((void**)&vl,  g_vl);
    cudaGetSymbolAddress((void**)&wh,  g_wh);
    cudaGetSymbolAddress((void**)&wl,  g_wl);

    cudaFuncSetAttribute(hgemm_proj, cudaFuncAttributeMaxDynamicSharedMemorySize, GEMM_SMEM);
    cudaFuncSetAttribute(hgemm_out,  cudaFuncAttributeMaxDynamicSharedMemorySize, GEMM_SMEM);
    cudaFuncSetAttribute(attn3_kernel, cudaFuncAttributeMaxDynamicSharedMemorySize, ATTN_SMEM);

    const size_t NSE = (size_t)B_ * S_ * E_;
    const size_t NEE = (size_t)E_ * E_;

    ln_split_kernel<<<B_ * S_, 256>>>(query, gamma, beta, qn, ash, asl);

    dim3 sgrid(B_ * S_ * E_ / 4 / 256, 2);
    split2_kernel<<<sgrid, 256>>>(key, value, ash, asl);

    dim3 tgrid(32, 32, 4);
    tsplit4_kernel<<<tgrid, 256>>>(wq, wk, wv, outw);

    dim3 ggrid(8, 32);
    hgemm_proj<<<ggrid, 256, GEMM_SMEM>>>(ash,           asl,           wh,           wl,           qh, ql);
    hgemm_proj<<<ggrid, 256, GEMM_SMEM>>>(ash + NSE,     asl + NSE,     wh + NEE,     wl + NEE,     kh, kl_);
    hgemm_proj<<<ggrid, 256, GEMM_SMEM>>>(ash + 2 * NSE, asl + 2 * NSE, wh + 2 * NEE, wl + 2 * NEE, vh, vl);

    dim3 agrid(S_ / 32, H_, B_);
    attn3_kernel<<<agrid, 256, ATTN_SMEM>>>(qh, ql, kh, kl_, vh, vl, klen, attn_out, ash, asl);

    hgemm_out<<<ggrid, 256, GEMM_SMEM>>>(ash, asl, out, outb, qn, qlen);
}

// round 17
// speedup vs baseline: 1.0771x; 1.0518x over previous
#include <cuda_runtime.h>
#include <cuda_bf16.h>
#include <math.h>
#include <stdint.h>

#define B_    4
#define S_    1024
#define E_    1024
#define H_    16
#define DH_   64

// ---------------- scratch ----------------
__device__ float g_qn [B_ * S_ * E_];
__device__ __nv_bfloat16 g_ash[3 * B_ * S_ * E_];
__device__ __nv_bfloat16 g_asl[3 * B_ * S_ * E_];
__device__ __nv_bfloat16 g_wh[4 * E_ * E_];
__device__ __nv_bfloat16 g_wl[4 * E_ * E_];
__device__ __nv_bfloat16 g_qh[B_ * S_ * E_];
__device__ __nv_bfloat16 g_ql[B_ * S_ * E_];
__device__ __nv_bfloat16 g_kh[B_ * S_ * E_];
__device__ __nv_bfloat16 g_kl[B_ * S_ * E_];
__device__ __nv_bfloat16 g_vh[B_ * S_ * E_];
__device__ __nv_bfloat16 g_vl[B_ * S_ * E_];
__device__ int g_kmap[B_ * S_];
__device__ int g_knlive;

// ---------------- PTX helpers ----------------
__device__ __forceinline__ uint32_t smem_u32(const void* p) {
    uint32_t a;
    asm("{ .reg .u64 t; cvta.to.shared.u64 t, %1; cvt.u32.u64 %0, t; }" : "=r"(a) : "l"(p));
    return a;
}
__device__ __forceinline__ void cp_async16(uint32_t s, const void* g) {
    asm volatile("cp.async.cg.shared.global [%0], [%1], 16;" :: "r"(s), "l"(g));
}
__device__ __forceinline__ void cp_commit() { asm volatile("cp.async.commit_group;" ::: "memory"); }
template<int N> __device__ __forceinline__ void cp_wait() { asm volatile("cp.async.wait_group %0;" :: "n"(N) : "memory"); }

__device__ __forceinline__ void ldmx4(uint32_t* r, uint32_t addr) {
    asm volatile("ldmatrix.sync.aligned.m8n8.x4.shared.b16 {%0,%1,%2,%3}, [%4];"
        : "=r"(r[0]), "=r"(r[1]), "=r"(r[2]), "=r"(r[3]) : "r"(addr));
}
__device__ __forceinline__ void ldmx4t(uint32_t* r, uint32_t addr) {
    asm volatile("ldmatrix.sync.aligned.m8n8.x4.trans.shared.b16 {%0,%1,%2,%3}, [%4];"
        : "=r"(r[0]), "=r"(r[1]), "=r"(r[2]), "=r"(r[3]) : "r"(addr));
}
__device__ __forceinline__ void mma16816(float* d, const uint32_t* a, const uint32_t* b) {
    asm volatile("mma.sync.aligned.m16n8k16.row.col.f32.bf16.bf16.f32 "
        "{%0,%1,%2,%3}, {%4,%5,%6,%7}, {%8,%9}, {%0,%1,%2,%3};"
        : "+f"(d[0]), "+f"(d[1]), "+f"(d[2]), "+f"(d[3])
        : "r"(a[0]), "r"(a[1]), "r"(a[2]), "r"(a[3]), "r"(b[0]), "r"(b[1]));
}
__device__ __forceinline__ uint32_t pack_bf2(__nv_bfloat16 a, __nv_bfloat16 b) {
    uint16_t ua = *(uint16_t*)&a, ub = *(uint16_t*)&b;
    return (uint32_t)ua | ((uint32_t)ub << 16);
}
__device__ __forceinline__ void split1(float v, __nv_bfloat16& h, __nv_bfloat16& l) {
    h = __float2bfloat16_rn(v);
    l = __float2bfloat16_rn(v - __bfloat162float(h));
}

// ---------------- K row map build ----------------
__global__ __launch_bounds__(256) void build_kmap_kernel(const int* __restrict__ klen) {
    __shared__ int gmax[4];
    __shared__ int off[5];
    int tid = threadIdx.x;
    if (tid < 4) gmax[tid] = (klen[tid] + 15) >> 4;
    __syncthreads();
    if (tid == 0) {
        off[0] = 0;
        for (int b = 0; b < 4; b++) off[b + 1] = off[b] + 16 * gmax[b];
        g_knlive = off[4];
    }
    __syncthreads();
    for (int idx = tid; idx < B_ * S_; idx += 256) g_kmap[idx] = 0;   // safe default
    __syncthreads();
    for (int b = 0; b < 4; b++) {
        int gm = gmax[b];
        int cnt = 16 * gm;
        for (int i = tid; i < cnt; i += 256) {
            int h = i / gm, g = i - h * gm;
            g_kmap[off[b] + i] = b * 1024 + h * 64 + g;
        }
    }
}

// ---------------- layernorm + Q split ----------------
__global__ __launch_bounds__(256) void ln_split_kernel(const float* __restrict__ x,
                                                       const float* __restrict__ gamma,
                                                       const float* __restrict__ beta,
                                                       float* __restrict__ y,
                                                       __nv_bfloat16* __restrict__ sh,
                                                       __nv_bfloat16* __restrict__ sl) {
    __shared__ float red[32];
    int row = blockIdx.x;
    int tid = threadIdx.x;
    const float* xr = x + (size_t)row * 1024;

    float v[4];
    float s = 0.f;
#pragma unroll
    for (int i = 0; i < 4; i++) { v[i] = xr[tid + 256 * i]; s += v[i]; }

    for (int off = 16; off; off >>= 1) s += __shfl_xor_sync(0xffffffffu, s, off);
    int lane = tid & 31, wid = tid >> 5;
    if (lane == 0) red[wid] = s;
    __syncthreads();
    if (wid == 0) {
        float t = (lane < 8) ? red[lane] : 0.f;
        for (int off = 4; off; off >>= 1) t += __shfl_xor_sync(0xffffffffu, t, off);
        if (lane == 0) red[0] = t;
    }
    __syncthreads();
    float mean = red[0] * (1.f / 1024.f);
    __syncthreads();

    float vs = 0.f;
#pragma unroll
    for (int i = 0; i < 4; i++) { float d = v[i] - mean; vs += d * d; }
    for (int off = 16; off; off >>= 1) vs += __shfl_xor_sync(0xffffffffu, vs, off);
    if (lane == 0) red[wid] = vs;
    __syncthreads();
    if (wid == 0) {
        float t = (lane < 8) ? red[lane] : 0.f;
        for (int off = 4; off; off >>= 1) t += __shfl_xor_sync(0xffffffffu, t, off);
        if (lane == 0) red[0] = t;
    }
    __syncthreads();
    float var = red[0] * (1.f / 1024.f);
    float rstd = rsqrtf(var + 1e-5f);

    float* yr = y + (size_t)row * 1024;
#pragma unroll
    for (int i = 0; i < 4; i++) {
        int c = tid + 256 * i;
        float o = (v[i] - mean) * rstd * gamma[c] + beta[c];
        yr[c] = o;
        __nv_bfloat16 hh, ll;
        split1(o, hh, ll);
        sh[(size_t)row * 1024 + c] = hh;
        sl[(size_t)row * 1024 + c] = ll;
    }
}

// ---------------- batched fp32 -> bf16 split (key, value) ----------------
__global__ __launch_bounds__(256) void split2_kernel(const float* __restrict__ key,
                                                     const float* __restrict__ value,
                                                     __nv_bfloat16* __restrict__ hi,
                                                     __nv_bfloat16* __restrict__ lo) {
    const float* x = blockIdx.y ? value : key;
    size_t slot = (size_t)(blockIdx.y + 1) * (B_ * S_ * E_);
    int i = blockIdx.x * 256 + threadIdx.x;
    float4 v = *(const float4*)(x + (size_t)i * 4);
    float f[4] = {v.x, v.y, v.z, v.w};
    __nv_bfloat16 h[4], l[4];
#pragma unroll
    for (int j = 0; j < 4; j++) split1(f[j], h[j], l[j]);
    *(uint2*)(hi + slot + (size_t)i * 4) = *(uint2*)h;
    *(uint2*)(lo + slot + (size_t)i * 4) = *(uint2*)l;
}

// ---------------- batched W -> W^T split ----------------
__global__ __launch_bounds__(256) void tsplit4_kernel(const float* __restrict__ w0,
                                                      const float* __restrict__ w1,
                                                      const float* __restrict__ w2,
                                                      const float* __restrict__ w3) {
    __shared__ float t[32][33];
    const float* W = (blockIdx.z == 0) ? w0 : (blockIdx.z == 1) ? w1 : (blockIdx.z == 2) ? w2 : w3;
    size_t slot = (size_t)blockIdx.z * (E_ * E_);
    int bx = blockIdx.x * 32;
    int by = blockIdx.y * 32;
    int x = threadIdx.x & 31, y = threadIdx.x >> 5;
#pragma unroll
    for (int i = 0; i < 32; i += 8)
        t[y + i][x] = W[(size_t)(by + y + i) * 1024 + bx + x];
    __syncthreads();
#pragma unroll
    for (int i = 0; i < 32; i += 8) {
        int n = bx + y + i, k = by + x;
        __nv_bfloat16 h, l;
        split1(t[x][y + i], h, l);
        g_wh[slot + (size_t)n * 1024 + k] = h;
        g_wl[slot + (size_t)n * 1024 + k] = l;
    }
}

// ---------------- HMMA bf16x3 GEMM core ----------------
// MODE 0: bf16 hi/lo out. MODE 1: fp32 out + bias/mask/residual. MODE 2: bf16 out, row-mapped.
#define LDK 40
static constexpr int MAT_H  = 128 * LDK;
static constexpr int GEMM_SMEM = 2 * 4 * MAT_H * 2;

template<int MODE>
__device__ __forceinline__ void hgemm_core(const __nv_bfloat16* Ah, const __nv_bfloat16* Al,
                                           const __nv_bfloat16* Bth, const __nv_bfloat16* Btl,
                                           float* C, __nv_bfloat16* Oh, __nv_bfloat16* Ol,
                                           const float* bias, const float* qn, const int* qlen,
                                           int row0, int col0, uint32_t sbase,
                                           const int* rowmap, int nlive) {
    const int tid = threadIdx.x;
    const int wid = tid >> 5, lane = tid & 31;

    const __nv_bfloat16* gp2 = Bth + (size_t)col0 * 1024;
    const __nv_bfloat16* gp3 = Btl + (size_t)col0 * 1024;

    const int lr = tid >> 2;
    const int lq = (tid & 3) * 8;

    // A-row bases (direct or mapped)
    size_t arow[2];
    if (MODE == 2) {
        arow[0] = (size_t)rowmap[row0 + lr] * 1024;
        arow[1] = (size_t)rowmap[row0 + lr + 64] * 1024;
    } else {
        arow[0] = (size_t)(row0 + lr) * 1024;
        arow[1] = (size_t)(row0 + lr + 64) * 1024;
    }

    auto load_stage = [&](int st, int kt) {
        uint32_t sb = sbase + (uint32_t)st * 4 * MAT_H * 2;
        int ko = kt * 32 + lq;
#pragma unroll
        for (int i = 0; i < 2; i++) {
            int r = lr + i * 64;
            cp_async16(sb + (uint32_t)(0 * MAT_H + r * LDK + lq) * 2, Ah + arow[i] + ko);
            cp_async16(sb + (uint32_t)(1 * MAT_H + r * LDK + lq) * 2, Al + arow[i] + ko);
            cp_async16(sb + (uint32_t)(2 * MAT_H + r * LDK + lq) * 2, gp2 + (size_t)r * 1024 + ko);
            cp_async16(sb + (uint32_t)(3 * MAT_H + r * LDK + lq) * 2, gp3 + (size_t)r * 1024 + ko);
        }
    };

    load_stage(0, 0);
    cp_commit();

    float acc[2][8][4];
#pragma unroll
    for (int mt = 0; mt < 2; mt++)
#pragma unroll
        for (int nt = 0; nt < 8; nt++)
#pragma unroll
            for (int j = 0; j < 4; j++) acc[mt][nt][j] = 0.f;

    const int warp_m = (wid & 3) * 32;
    const int warp_n = (wid >> 2) * 64;

    const uint32_t a_off = (uint32_t)((warp_m + (lane & 15)) * LDK + (lane >> 4) * 8);
    const uint32_t b_off = (uint32_t)((warp_n + (lane >> 4) * 8 + (lane & 7)) * LDK + ((lane >> 3) & 1) * 8);

    for (int kt = 0; kt < 32; kt++) {
        const int st = kt & 1;
        if (kt + 1 < 32) {
            load_stage(st ^ 1, kt + 1);
            cp_commit();
            cp_wait<1>();
        } else {
            cp_wait<0>();
        }
        __syncthreads();

        const uint32_t Abase = sbase + (uint32_t)st * 4 * MAT_H * 2;
        const uint32_t Bbase = Abase + 2 * MAT_H * 2;
#pragma unroll
        for (int ks = 0; ks < 2; ks++) {
            const uint32_t kadd = (uint32_t)(ks * 16) * 2;
            uint32_t a_h[2][4], a_l[2][4];
#pragma unroll
            for (int mt = 0; mt < 2; mt++) {
                uint32_t off = (a_off + (uint32_t)(mt * 16) * LDK) * 2 + kadd;
                ldmx4(a_h[mt], Abase + off);
                ldmx4(a_l[mt], Abase + MAT_H * 2 + off);
            }
#pragma unroll
            for (int np = 0; np < 4; np++) {
                uint32_t b_h[4], b_l[4];
                uint32_t off = (b_off + (uint32_t)(np * 16) * LDK) * 2 + kadd;
                ldmx4(b_h, Bbase + off);
                ldmx4(b_l, Bbase + MAT_H * 2 + off);
#pragma unroll
                for (int mt = 0; mt < 2; mt++) {
                    mma16816(acc[mt][np * 2 + 0], a_h[mt], b_h + 0);
                    mma16816(acc[mt][np * 2 + 0], a_h[mt], b_l + 0);
                    mma16816(acc[mt][np * 2 + 0], a_l[mt], b_h + 0);
                    mma16816(acc[mt][np * 2 + 1], a_h[mt], b_h + 2);
                    mma16816(acc[mt][np * 2 + 1], a_h[mt], b_l + 2);
                    mma16816(acc[mt][np * 2 + 1], a_l[mt], b_h + 2);
                }
            }
        }
        __syncthreads();
    }

#pragma unroll
    for (int mt = 0; mt < 2; mt++) {
        int r_log0 = row0 + warp_m + mt * 16 + (lane >> 2);
#pragma unroll
        for (int half = 0; half < 2; half++) {
            int r_log = r_log0 + half * 8;
            int r = r_log;
            bool live = true;
            if (MODE == 2) {
                live = (r_log < nlive);
                r = live ? rowmap[r_log] : 0;
            }
            float keep = 1.f;
            if (MODE == 1) {
                int bb = r >> 10, ss = r & 1023;
                keep = (ss < qlen[bb]) ? 1.f : 0.f;
            }
#pragma unroll
            for (int nt = 0; nt < 8; nt++) {
                int c = col0 + warp_n + nt * 8 + (lane & 3) * 2;
                float v0 = acc[mt][nt][half * 2 + 0];
                float v1 = acc[mt][nt][half * 2 + 1];
                if (MODE == 1) {
                    const float2 bi = *(const float2*)&bias[c];
                    const float2 q2 = *(const float2*)&qn[(size_t)r * 1024 + c];
                    v0 = (v0 + bi.x) * keep + q2.x;
                    v1 = (v1 + bi.y) * keep + q2.y;
                    *(float2*)&C[(size_t)r * 1024 + c] = make_float2(v0, v1);
                } else {
                    if (MODE == 2 && !live) continue;
                    __nv_bfloat16 h0, h1, l0, l1;
                    split1(v0, h0, l0);
                    split1(v1, h1, l1);
                    *(uint32_t*)&Oh[(size_t)r * 1024 + c] = pack_bf2(h0, h1);
                    *(uint32_t*)&Ol[(size_t)r * 1024 + c] = pack_bf2(l0, l1);
                }
            }
        }
    }
}

__global__ __launch_bounds__(256) void hgemm_proj(const __nv_bfloat16* __restrict__ ash,
                                                  const __nv_bfloat16* __restrict__ asl,
                                                  const __nv_bfloat16* __restrict__ wth,
                                                  const __nv_bfloat16* __restrict__ wtl,
                                                  __nv_bfloat16* __restrict__ oh,
                                                  __nv_bfloat16* __restrict__ ol) {
    extern __shared__ __nv_bfloat16 smb[];
    hgemm_core<0>(ash, asl, wth, wtl, nullptr, oh, ol, nullptr, nullptr, nullptr,
                  blockIdx.y * 128, blockIdx.x * 128, smem_u32(smb), nullptr, 0);
}

// K projection with row compaction
__global__ __launch_bounds__(256) void hgemm_kproj(const __nv_bfloat16* __restrict__ ash,
                                                   const __nv_bfloat16* __restrict__ asl,
                                                   const __nv_bfloat16* __restrict__ wth,
                                                   const __nv_bfloat16* __restrict__ wtl,
                                                   __nv_bfloat16* __restrict__ oh,
                                                   __nv_bfloat16* __restrict__ ol) {
    extern __shared__ __nv_bfloat16 smb[];
    int row0 = blockIdx.y * 128;
    int nlive = g_knlive;
    if (row0 >= nlive) return;
    hgemm_core<2>(ash, asl, wth, wtl, nullptr, oh, ol, nullptr, nullptr, nullptr,
                  row0, blockIdx.x * 128, smem_u32(smb), g_kmap, nlive);
}

__global__ __launch_bounds__(256) void hgemm_out(const __nv_bfloat16* __restrict__ ash,
                                                 const __nv_bfloat16* __restrict__ asl,
                                                 float* __restrict__ C,
                                                 const float* __restrict__ bias,
                                                 const float* __restrict__ qn,
                                                 const int* __restrict__ qlen) {
    extern __shared__ __nv_bfloat16 smb[];
    int row0 = blockIdx.y * 128;
    int col0 = blockIdx.x * 128;
    {
        int bb = row0 >> 10, ss = row0 & 1023;
        if (ss >= qlen[bb]) {
            int tid = threadIdx.x;
            int r = row0 + (tid >> 1);
            int c0 = col0 + (tid & 1) * 64;
            const float4* src = (const float4*)&qn[(size_t)r * 1024 + c0];
            float4* dst = (float4*)&C[(size_t)r * 1024 + c0];
#pragma unroll
            for (int i = 0; i < 16; i++) dst[i] = src[i];
            return;
        }
    }
    hgemm_core<1>(ash, asl, g_wh + (size_t)3 * E_ * E_, g_wl + (size_t)3 * E_ * E_,
                  C, nullptr, nullptr, bias, qn, qlen,
                  row0, col0, smem_u32(smb), nullptr, 0);
}

// ---------------- fused attention ----------------
#define EPAD 1048
static constexpr int A_SQH = 0;
static constexpr int A_SQL = 2304;
static constexpr int A_SK  = 4608;
static constexpr int A_SEH = 41472;
static constexpr int A_SEL = 75008;
static constexpr int ATTN_SMEM = 217088 + 256;

__global__ __launch_bounds__(256) void attn3_kernel(const __nv_bfloat16* __restrict__ qh,
                                                    const __nv_bfloat16* __restrict__ ql,
                                                    const __nv_bfloat16* __restrict__ kh,
                                                    const __nv_bfloat16* __restrict__ kl_,
                                                    const __nv_bfloat16* __restrict__ vh,
                                                    const __nv_bfloat16* __restrict__ vl,
                                                    const int* __restrict__ klen,
                                                    float* __restrict__ attn_out,
                                                    __nv_bfloat16* __restrict__ ctx_h,
                                                    __nv_bfloat16* __restrict__ ctx_l) {
    extern __shared__ __nv_bfloat16 smb[];
    const uint32_t sb = smem_u32(smb);
    float* sZ = (float*)((char*)smb + 217088);

    const int b = blockIdx.z;
    const int h = blockIdx.y;
    const int q0 = blockIdx.x * 32;
    const int tid = threadIdx.x;
    const int wid = tid >> 5, lane = tid & 31;
    const int kl = klen[b];
    const int nact = (kl + 127) >> 7;

    const size_t base = (size_t)b * (S_ * E_);

    // Q load
    {
        int row = tid >> 3, seg = (tid & 7) * 8;
        int s = q0 + row;
        size_t ga = base + (size_t)((h << 6) + (s >> 4)) * 1024 + ((s & 15) << 6) + seg;
        cp_async16(sb + (uint32_t)(A_SQH + row * 72 + seg) * 2, qh + ga);
        cp_async16(sb + (uint32_t)(A_SQL + row * 72 + seg) * 2, ql + ga);
    }

    auto load_kv = [&](const __nv_bfloat16* ph, const __nv_bfloat16* pl, int ch, int buf) {
        uint32_t kb = sb + (uint32_t)(A_SK + buf * 18432) * 2;
#pragma unroll
        for (int i = 0; i < 4; i++) {
            int idx = tid + i * 256;
            int j = idx >> 3, seg = (idx & 7) * 8;
            int t = ch * 128 + j;
            size_t ga = base + (size_t)((h << 6) + (t >> 4)) * 1024 + ((t & 15) << 6) + seg;
            uint32_t sa = kb + (uint32_t)(j * 72 + seg) * 2;
            cp_async16(sa, ph + ga);
            cp_async16(sa + 9216 * 2, pl + ga);
        }
    };

    load_kv(kh, kl_, 0, 0);
    cp_commit();

    // fill masked sE region; init sZ with analytic masked contribution
    {
        if (tid < 32) sZ[tid] = (float)(1024 - nact * 128);
        int t0 = nact * 128;
        int npairs = (1024 - t0) >> 1;
        if (npairs > 0) {
            uint32_t onepair = pack_bf2(__float2bfloat16_rn(1.f), __float2bfloat16_rn(1.f));
            for (int idx = tid; idx < 32 * npairs; idx += 256) {
                int r = idx / npairs;
                int p = idx - r * npairs;
                int t = t0 + p * 2;
                *(uint32_t*)&smb[A_SEH + r * EPAD + t] = onepair;
                *(uint32_t*)&smb[A_SEL + r * EPAD + t] = 0u;
            }
        }
    }

    const int mt = wid & 1;
    const int ng = wid >> 1;

    const uint32_t qa_off = (uint32_t)((mt * 16 + (lane & 15)) * 72 + (lane >> 4) * 8);
    const uint32_t kb_off = (uint32_t)((ng * 32 + (lane >> 4) * 8 + (lane & 7)) * 72 + ((lane >> 3) & 1) * 8);

    float zp0 = 0.f, zp1 = 0.f;

    // QK chunks
    for (int ch = 0; ch < nact; ch++) {
        cp_wait<0>();
        __syncthreads();
        if (ch + 1 < nact) { load_kv(kh, kl_, ch + 1, (ch + 1) & 1); cp_commit(); }

        const uint32_t Kb = sb + (uint32_t)(A_SK + (ch & 1) * 18432) * 2;
        float acc[4][4];
#pragma unroll
        for (int j = 0; j < 4; j++)
#pragma unroll
            for (int k = 0; k < 4; k++) acc[j][k] = 0.f;

#pragma unroll
        for (int ks = 0; ks < 4; ks++) {
            uint32_t a_h[4], a_l[4];
            uint32_t aoff = (qa_off + ks * 16) * 2;
            ldmx4(a_h, sb + A_SQH * 2 + aoff);
            ldmx4(a_l, sb + A_SQL * 2 + aoff);
            uint32_t b_h[2][4], b_l[2][4];
#pragma unroll
            for (int np = 0; np < 2; np++) {
                uint32_t boff = (kb_off + np * 16 * 72 + ks * 16) * 2;
                ldmx4(b_h[np], Kb + boff);
                ldmx4(b_l[np], Kb + 9216 * 2 + boff);
            }
            mma16816(acc[0], a_h, b_h[0] + 0);
            mma16816(acc[1], a_h, b_h[0] + 2);
            mma16816(acc[2], a_h, b_h[1] + 0);
            mma16816(acc[3], a_h, b_h[1] + 2);
            mma16816(acc[0], a_h, b_l[0] + 0);
            mma16816(acc[1], a_h, b_l[0] + 2);
            mma16816(acc[2], a_h, b_l[1] + 0);
            mma16816(acc[3], a_h, b_l[1] + 2);
            mma16816(acc[0], a_l, b_h[0] + 0);
            mma16816(acc[1], a_l, b_h[0] + 2);
            mma16816(acc[2], a_l, b_h[1] + 0);
            mma16816(acc[3], a_l, b_h[1] + 2);
        }

        int r1 = mt * 16 + (lane >> 2);
#pragma unroll
        for (int j = 0; j < 4; j++) {
            int c = ch * 128 + ng * 32 + j * 8 + (lane & 3) * 2;
#pragma unroll
            for (int half = 0; half < 2; half++) {
                int r = r1 + half * 8;
                float e0 = (c < kl)     ? __expf(acc[j][half * 2 + 0] * 0.125f) : 1.f;
                float e1 = (c + 1 < kl) ? __expf(acc[j][half * 2 + 1] * 0.125f) : 1.f;
                if (half == 0) zp0 += e0 + e1; else zp1 += e0 + e1;
                __nv_bfloat16 h0, h1, l0, l1;
                split1(e0, h0, l0);
                split1(e1, h1, l1);
                *(uint32_t*)&smb[A_SEH + r * EPAD + c] = pack_bf2(h0, h1);
                *(uint32_t*)&smb[A_SEL + r * EPAD + c] = pack_bf2(l0, l1);
            }
        }
    }
    cp_wait<0>();

    zp0 += __shfl_xor_sync(0xffffffffu, zp0, 1);
    zp0 += __shfl_xor_sync(0xffffffffu, zp0, 2);
    zp1 += __shfl_xor_sync(0xffffffffu, zp1, 1);
    zp1 += __shfl_xor_sync(0xffffffffu, zp1, 2);
    if ((lane & 3) == 0) {
        int r1 = mt * 16 + (lane >> 2);
        atomicAdd(&sZ[r1], zp0);
        atomicAdd(&sZ[r1 + 8], zp1);
    }
    __syncthreads();

    load_kv(vh, vl, 0, 0);
    cp_commit();
    if (tid < 32) sZ[tid] = 1.f / sZ[tid];
    __syncthreads();

    const uint32_t ea_base = (uint32_t)((mt * 16 + (lane & 15)) * EPAD + (lane >> 4) * 8);
    const uint32_t vbt_off = (uint32_t)(((lane & 7) + ((lane >> 3) & 1) * 8) * 72 + ng * 16 + ((lane >> 4) & 1) * 8);

    float cacc[2][4];
#pragma unroll
    for (int j = 0; j < 2; j++)
#pragma unroll
        for (int k = 0; k < 4; k++) cacc[j][k] = 0.f;

    size_t abase = 0;
    if (attn_out) abase = (((size_t)b * H_ + h) * S_ + q0) * (size_t)S_;

    for (int ch = 0; ch < 8; ch++) {
        cp_wait<0>();
        __syncthreads();
        if (ch + 1 < 8) { load_kv(vh, vl, ch + 1, (ch + 1) & 1); cp_commit(); }

        if (attn_out) {
#pragma unroll
            for (int rr = 0; rr < 4; rr++) {
                int r = wid * 4 + rr;
                float invZ = sZ[r];
                int t = ch * 128 + lane * 4;
                uint2 ph = *(uint2*)&smb[A_SEH + r * EPAD + t];
                uint2 pl = *(uint2*)&smb[A_SEL + r * EPAD + t];
                __nv_bfloat162 h01 = *(__nv_bfloat162*)&ph.x;
                __nv_bfloat162 h23 = *(__nv_bfloat162*)&ph.y;
                __nv_bfloat162 l01 = *(__nv_bfloat162*)&pl.x;
                __nv_bfloat162 l23 = *(__nv_bfloat162*)&pl.y;
                float4 p;
                p.x = (__bfloat162float(h01.x) + __bfloat162float(l01.x)) * invZ;
                p.y = (__bfloat162float(h01.y) + __bfloat162float(l01.y)) * invZ;
                p.z = (__bfloat162float(h23.x) + __bfloat162float(l23.x)) * invZ;
                p.w = (__bfloat162float(h23.y) + __bfloat162float(l23.y)) * invZ;
                *(float4*)&attn_out[abase + (size_t)r * S_ + t] = p;
            }
        }

        const uint32_t Vb = sb + (uint32_t)(A_SK + (ch & 1) * 18432) * 2;
#pragma unroll
        for (int ks = 0; ks < 8; ks++) {
            uint32_t a_h[4], a_l[4];
            uint32_t aoff = (ea_base + ch * 128 + ks * 16) * 2;
            ldmx4(a_h, sb + A_SEH * 2 + aoff);
            ldmx4(a_l, sb + A_SEL * 2 + aoff);
            uint32_t b_h[4], b_l[4];
            uint32_t boff = (vbt_off + (uint32_t)(ks * 16) * 72) * 2;
            ldmx4t(b_h, Vb + boff);
            ldmx4t(b_l, Vb + 9216 * 2 + boff);
            mma16816(cacc[0], a_h, b_h + 0);
            mma16816(cacc[0], a_h, b_l + 0);
            mma16816(cacc[0], a_l, b_h + 0);
            mma16816(cacc[1], a_h, b_h + 2);
            mma16816(cacc[1], a_h, b_l + 2);
            mma16816(cacc[1], a_l, b_h + 2);
        }
    }

    // ctx write
    {
        int r1 = mt * 16 + (lane >> 2);
#pragma unroll
        for (int j = 0; j < 2; j++) {
            int c = ng * 16 + j * 8 + (lane & 3) * 2;
#pragma unroll
            for (int half = 0; half < 2; half++) {
                int r = r1 + half * 8;
                float invZ = sZ[r];
                float v0 = cacc[j][half * 2 + 0] * invZ;
                float v1 = cacc[j][half * 2 + 1] * invZ;
                __nv_bfloat16 h0, h1, l0, l1;
                split1(v0, h0, l0);
                split1(v1, h1, l1);
                size_t oa = (size_t)(b * 1024 + q0 + r) * 1024 + (h << 6) + c;
                *(uint32_t*)&ctx_h[oa] = pack_bf2(h0, h1);
                *(uint32_t*)&ctx_l[oa] = pack_bf2(l0, l1);
            }
        }
    }
}

// ---------------- launcher ----------------
extern "C" void kernel_launch(void* const* d_in, const int* in_sizes, int n_in,
                              void* d_out, int out_size) {
    const float* query = (const float*)d_in[0];
    const float* key   = (const float*)d_in[1];
    const float* value = (const float*)d_in[2];
    const int*   qlen  = (const int*)d_in[3];
    const int*   klen  = (const int*)d_in[4];
    const float* wq    = (const float*)d_in[5];
    const float* wk    = (const float*)d_in[6];
    const float* wv    = (const float*)d_in[7];
    const float* gamma = (const float*)d_in[8];
    const float* beta  = (const float*)d_in[9];
    const float* outw  = (const float*)d_in[10];
    const float* outb  = (const float*)d_in[11];

    float* out = (float*)d_out;
    const long long n_skip = (long long)B_ * S_ * E_;
    const long long n_attn = (long long)B_ * H_ * S_ * (long long)S_;
    float* attn_out = ((long long)out_size >= n_skip + n_attn) ? (out + n_skip) : nullptr;

    float* qn;
    __nv_bfloat16 *ash, *asl, *qh, *ql, *kh, *kl_, *vh, *vl, *wh, *wl;
    cudaGetSymbolAddress((void**)&qn,  g_qn);
    cudaGetSymbolAddress((void**)&ash, g_ash);
    cudaGetSymbolAddress((void**)&asl, g_asl);
    cudaGetSymbolAddress((void**)&qh,  g_qh);
    cudaGetSymbolAddress((void**)&ql,  g_ql);
    cudaGetSymbolAddress((void**)&kh,  g_kh);
    cudaGetSymbolAddress((void**)&kl_, g_kl);
    cudaGetSymbolAddress((void**)&vh,  g_vh);
    cudaGetSymbolAddress((void**)&vl,  g_vl);
    cudaGetSymbolAddress((void**)&wh,  g_wh);
    cudaGetSymbolAddress((void**)&wl,  g_wl);

    cudaFuncSetAttribute(hgemm_proj,  cudaFuncAttributeMaxDynamicSharedMemorySize, GEMM_SMEM);
    cudaFuncSetAttribute(hgemm_kproj, cudaFuncAttributeMaxDynamicSharedMemorySize, GEMM_SMEM);
    cudaFuncSetAttribute(hgemm_out,   cudaFuncAttributeMaxDynamicSharedMemorySize, GEMM_SMEM);
    cudaFuncSetAttribute(attn3_kernel, cudaFuncAttributeMaxDynamicSharedMemorySize, ATTN_SMEM);

    const size_t NSE = (size_t)B_ * S_ * E_;
    const size_t NEE = (size_t)E_ * E_;

    build_kmap_kernel<<<1, 256>>>(klen);

    ln_split_kernel<<<B_ * S_, 256>>>(query, gamma, beta, qn, ash, asl);

    dim3 sgrid(B_ * S_ * E_ / 4 / 256, 2);
    split2_kernel<<<sgrid, 256>>>(key, value, ash, asl);

    dim3 tgrid(32, 32, 4);
    tsplit4_kernel<<<tgrid, 256>>>(wq, wk, wv, outw);

    dim3 ggrid(8, 32);
    hgemm_proj <<<ggrid, 256, GEMM_SMEM>>>(ash,           asl,           wh,           wl,           qh, ql);
    hgemm_kproj<<<ggrid, 256, GEMM_SMEM>>>(ash + NSE,     asl + NSE,     wh + NEE,     wl + NEE,     kh, kl_);
    hgemm_proj <<<ggrid, 256, GEMM_SMEM>>>(ash + 2 * NSE, asl + 2 * NSE, wh + 2 * NEE, wl + 2 * NEE, vh, vl);

    dim3 agrid(S_ / 32, H_, B_);
    attn3_kernel<<<agrid, 256, ATTN_SMEM>>>(qh, ql, kh, kl_, vh, vl, klen, attn_out, ash, asl);

    hgemm_out<<<ggrid, 256, GEMM_SMEM>>>(ash, asl, out, outb, qn, qlen);
}